// round 2
// baseline (speedup 1.0000x reference)
#include <cuda_runtime.h>

#define TT  128
#define BSZ 64
#define DD  1024
#define HH  1024
#define NG  4096   // 4*H

typedef unsigned long long u64;

// Scratch (device globals: no allocation allowed in kernel_launch)
__device__ float g_G[(size_t)TT * BSZ * NG];   // precomputed x@Wx + b, 128 MB
__device__ float g_c[BSZ * HH];                // cell state, 256 KB

__device__ __forceinline__ u64 fma2(u64 a, u64 b, u64 c) {
    u64 d;
    asm("fma.rn.f32x2 %0, %1, %2, %3;" : "=l"(d) : "l"(a), "l"(b), "l"(c));
    return d;
}
__device__ __forceinline__ u64 pack2(float lo, float hi) {
    u64 d;
    asm("mov.b64 %0, {%1, %2};" : "=l"(d) : "f"(lo), "f"(hi));
    return d;
}
__device__ __forceinline__ void unpack2(u64 v, float& lo, float& hi) {
    asm("mov.b64 {%0, %1}, %2;" : "=f"(lo), "=f"(hi) : "l"(v));
}

// ---------------------------------------------------------------------------
// Phase 1: G[M=8192, N=4096] = X[8192,1024] @ Wx[1024,4096] + b
// 128x128 tile, BK=8, 256 threads, 8x8 per thread.
// f32x2 pairs COLUMNS (natural float pairs in Bs); A is stored pre-duplicated
// (a,a) as u64 at smem-fill time -> zero packs in the inner loop.
// ---------------------------------------------------------------------------
__global__ __launch_bounds__(256) void gemm_pre(const float* __restrict__ X,
                                                const float* __restrict__ Wx,
                                                const float* __restrict__ bias) {
    const int N = NG, K = DD;
    __shared__ u64   AsD[2][8][128];  // [k][m] duplicated (a,a)
    __shared__ float Bs[2][8][128];   // [k][n]

    const int tid  = threadIdx.x;
    const int bx   = blockIdx.x;   // N/128
    const int by   = blockIdx.y;   // M/128
    const int aRow = tid >> 1;         // 0..127
    const int aK4  = (tid & 1) << 2;   // 0 or 4
    const int bK   = tid >> 5;         // 0..7
    const int bN4  = (tid & 31) << 2;  // 0..124
    const int tx   = tid & 15;
    const int ty   = tid >> 4;

    const float* Ap = X  + (size_t)(by * 128) * K;
    const float* Bp = Wx + (size_t)(bx * 128);

    float4 aR = *(const float4*)(Ap + (size_t)aRow * K + aK4);
    float4 bR = *(const float4*)(Bp + (size_t)bK * N + bN4);
    AsD[0][aK4 + 0][aRow] = pack2(aR.x, aR.x);
    AsD[0][aK4 + 1][aRow] = pack2(aR.y, aR.y);
    AsD[0][aK4 + 2][aRow] = pack2(aR.z, aR.z);
    AsD[0][aK4 + 3][aRow] = pack2(aR.w, aR.w);
    *(float4*)&Bs[0][bK][bN4] = bR;
    __syncthreads();

    u64 acc[8][4];   // 8 rows x 4 col-pairs
    #pragma unroll
    for (int i = 0; i < 8; ++i)
        #pragma unroll
        for (int j = 0; j < 4; ++j) acc[i][j] = 0ull;

    const int nT = K / 8;  // 128 k-tiles
    for (int tk = 0; tk < nT; ++tk) {
        const int cur = tk & 1;
        if (tk + 1 < nT) {
            const int k0 = (tk + 1) * 8;
            aR = *(const float4*)(Ap + (size_t)aRow * K + k0 + aK4);
            bR = *(const float4*)(Bp + (size_t)(k0 + bK) * N + bN4);
        }
        #pragma unroll
        for (int kk = 0; kk < 8; ++kk) {
            const u64* ap = &AsD[cur][kk][ty * 8];
            ulonglong2 a0 = *(const ulonglong2*)(ap + 0);
            ulonglong2 a1 = *(const ulonglong2*)(ap + 2);
            ulonglong2 a2 = *(const ulonglong2*)(ap + 4);
            ulonglong2 a3 = *(const ulonglong2*)(ap + 6);
            u64 am[8] = {a0.x, a0.y, a1.x, a1.y, a2.x, a2.y, a3.x, a3.y};
            ulonglong2 b0 = *(const ulonglong2*)&Bs[cur][kk][tx * 8];
            ulonglong2 b1 = *(const ulonglong2*)&Bs[cur][kk][tx * 8 + 4];
            u64 bp[4] = {b0.x, b0.y, b1.x, b1.y};
            #pragma unroll
            for (int i = 0; i < 8; ++i)
                #pragma unroll
                for (int j = 0; j < 4; ++j)
                    acc[i][j] = fma2(am[i], bp[j], acc[i][j]);
        }
        if (tk + 1 < nT) {
            const int nxt = cur ^ 1;
            AsD[nxt][aK4 + 0][aRow] = pack2(aR.x, aR.x);
            AsD[nxt][aK4 + 1][aRow] = pack2(aR.y, aR.y);
            AsD[nxt][aK4 + 2][aRow] = pack2(aR.z, aR.z);
            AsD[nxt][aK4 + 3][aRow] = pack2(aR.w, aR.w);
            *(float4*)&Bs[nxt][bK][bN4] = bR;
            __syncthreads();
        }
    }

    // Epilogue: G = acc + b (col-pairs -> float2 stores)
    float* Gp = g_G + (size_t)(by * 128) * N + (size_t)(bx * 128);
    #pragma unroll
    for (int i = 0; i < 8; ++i) {
        const int row = ty * 8 + i;
        #pragma unroll
        for (int j = 0; j < 4; ++j) {
            const int col = tx * 8 + 2 * j;
            float lo, hi;
            unpack2(acc[i][j], lo, hi);
            const float2 bv = *(const float2*)&bias[bx * 128 + col];
            float2 o; o.x = lo + bv.x; o.y = hi + bv.y;
            *(float2*)&Gp[(size_t)row * N + col] = o;
        }
    }
}

// ---------------------------------------------------------------------------
// Phase 2: one kernel per timestep.
// CTA `cta` owns gate-cols {gate*1024 + cta*8 + hl} (32 cols), all 64 rows.
// 512 threads = 8 k-groups (K_s=128) x 64 threads; thread tile 8 rows x 4 cols
// => 16 fma2 per k for 64B of LDS (4x better ratio than round 1).
// Weights staged pre-duplicated (w,w); h staged transposed (row-pairs via
// LDS.128). 8-way k-partials reduced through a padded smem stash.
// ---------------------------------------------------------------------------
#define STEP_THREADS 512
#define KG 8          // k-groups
#define KS 128        // k per group
#define CK 8          // k chunk per staging buffer
#define NCHUNK (KS / CK)   // 16
// dynamic smem layout (bytes):
//  hT: [kg][2][CK][64] float   -> 8*2*8*64*4   = 32768
//  wD: [kg][2][CK][32] u64     -> 8*2*8*32*8   = 32768  (offset 32768)
//  ps: [kg][64][37]    float   -> 8*64*37*4    = 75776  (offset 65536)
#define SMEM_STEP_BYTES (65536 + 75776)

__global__ __launch_bounds__(STEP_THREADS) void lstm_step(const float* __restrict__ Wh,
                                                          float* __restrict__ out,
                                                          int t) {
    extern __shared__ char smem[];
    float* hT = (float*)smem;
    u64*   wD = (u64*)(smem + 32768);
    float* ps = (float*)(smem + 65536);

    const int tid = threadIdx.x;
    const int cta = blockIdx.x;          // 0..127
    const int kg  = tid >> 6;            // 0..7
    const int v   = tid & 63;
    const int rg  = v >> 3;              // 0..7 -> rows rg*8..rg*8+7
    const int cg  = v & 7;               // 0..7 -> cols cg*4..cg*4+3
    const int r0  = rg * 8;
    const int j0  = cg * 4;

    u64 acc[4][4];
    #pragma unroll
    for (int i = 0; i < 4; ++i)
        #pragma unroll
        for (int j = 0; j < 4; ++j) acc[i][j] = 0ull;

    if (t > 0) {
        const float* hprev = out + (size_t)(t - 1) * BSZ * HH;
        const int kbase = kg * KS;
        // staging roles within the 64-thread group
        const int hRow = v;                       // h: one row, 8 consecutive k
        const int wkk  = v >> 3;                  // w: kk index 0..7
        const int jj   = (v & 7) * 4;             // w: 4 consecutive j-cols
        const int wcol = (jj >> 3) * HH + cta * 8 + (jj & 7);

        float* hTg = hT + kg * (2 * CK * 64);     // per-group staging
        u64*   wDg = wD + kg * (2 * CK * 32);

        const float* hSrc = hprev + (size_t)hRow * HH + kbase;
        const float* wSrc = Wh + (size_t)(kbase + wkk) * NG + wcol;

        // prologue: chunk 0
        float4 h0 = *(const float4*)(hSrc);
        float4 h1 = *(const float4*)(hSrc + 4);
        float4 wv = *(const float4*)(wSrc);
        {
            float hv[8] = {h0.x, h0.y, h0.z, h0.w, h1.x, h1.y, h1.z, h1.w};
            #pragma unroll
            for (int kk = 0; kk < 8; ++kk) hTg[kk * 64 + hRow] = hv[kk];
            u64* wdst = wDg + wkk * 32 + jj;
            wdst[0] = pack2(wv.x, wv.x);
            wdst[1] = pack2(wv.y, wv.y);
            wdst[2] = pack2(wv.z, wv.z);
            wdst[3] = pack2(wv.w, wv.w);
        }
        __syncthreads();

        for (int tk = 0; tk < NCHUNK; ++tk) {
            const int cur = tk & 1;
            if (tk + 1 < NCHUNK) {
                const int k0 = (tk + 1) * CK;
                h0 = *(const float4*)(hSrc + k0);
                h1 = *(const float4*)(hSrc + k0 + 4);
                wv = *(const float4*)(wSrc + (size_t)k0 * NG);
            }
            const float* hb = hTg + cur * (CK * 64);
            const u64*   wb = wDg + cur * (CK * 32);
            #pragma unroll
            for (int kk = 0; kk < CK; ++kk) {
                ulonglong2 hA = *(const ulonglong2*)(hb + kk * 64 + r0);
                ulonglong2 hB = *(const ulonglong2*)(hb + kk * 64 + r0 + 4);
                ulonglong2 wA = *(const ulonglong2*)(wb + kk * 32 + j0);
                ulonglong2 wB = *(const ulonglong2*)(wb + kk * 32 + j0 + 2);
                u64 hp[4] = {hA.x, hA.y, hB.x, hB.y};
                u64 wd[4] = {wA.x, wA.y, wB.x, wB.y};
                #pragma unroll
                for (int i = 0; i < 4; ++i)
                    #pragma unroll
                    for (int j = 0; j < 4; ++j)
                        acc[i][j] = fma2(hp[i], wd[j], acc[i][j]);
            }
            if (tk + 1 < NCHUNK) {
                const int nxt = cur ^ 1;
                float* hdsts = hTg + nxt * (CK * 64);
                u64*   wdsts = wDg + nxt * (CK * 32);
                float hv[8] = {h0.x, h0.y, h0.z, h0.w, h1.x, h1.y, h1.z, h1.w};
                #pragma unroll
                for (int kk = 0; kk < 8; ++kk) hdsts[kk * 64 + hRow] = hv[kk];
                u64* wdst = wdsts + wkk * 32 + jj;
                wdst[0] = pack2(wv.x, wv.x);
                wdst[1] = pack2(wv.y, wv.y);
                wdst[2] = pack2(wv.z, wv.z);
                wdst[3] = pack2(wv.w, wv.w);
                __syncthreads();
            }
        }

        // stash partials: ps[kg][row][j], pad 37
        #pragma unroll
        for (int i = 0; i < 4; ++i) {
            #pragma unroll
            for (int j = 0; j < 4; ++j) {
                float lo, hi;
                unpack2(acc[i][j], lo, hi);
                ps[(kg * 64 + r0 + 2 * i)     * 37 + j0 + j] = lo;
                ps[(kg * 64 + r0 + 2 * i + 1) * 37 + j0 + j] = hi;
            }
        }
    }
    __syncthreads();

    // Epilogue: 512 threads -> 512 h outputs (64 rows x 8 h-cols)
    const int row  = tid >> 3;
    const int hl   = tid & 7;
    const int ncol = cta * 8 + hl;
    const float* Grow = g_G + (size_t)t * BSZ * NG + (size_t)row * NG;
    float gi = Grow[ncol];
    float gf = Grow[HH + ncol];
    float gg = Grow[2 * HH + ncol];
    float go = Grow[3 * HH + ncol];
    if (t > 0) {
        #pragma unroll
        for (int g = 0; g < KG; ++g) {
            const int base = (g * 64 + row) * 37;
            gi += ps[base + hl];
            gf += ps[base + 8 + hl];
            gg += ps[base + 16 + hl];
            go += ps[base + 24 + hl];
        }
    }
    const float iv = __saturatef(gi + 0.5f);
    const float fv = __saturatef(gf + 0.5f);
    const float gv = fminf(fmaxf(gg, -1.0f), 1.0f);
    const float ov = __saturatef(go + 0.5f);
    const float cold = (t > 0) ? g_c[row * HH + ncol] : 0.0f;
    const float cnew = fv * cold + iv * gv;
    const float hnew = ov * fminf(fmaxf(cnew, -1.0f), 1.0f);
    g_c[row * HH + ncol] = cnew;
    out[(size_t)t * BSZ * HH + (size_t)row * HH + ncol] = hnew;
}

// ---------------------------------------------------------------------------
extern "C" void kernel_launch(void* const* d_in, const int* in_sizes, int n_in,
                              void* d_out, int out_size) {
    const float* x  = (const float*)d_in[0];   // [T, B, D]
    const float* Wx = (const float*)d_in[1];   // [D, 4H]
    const float* Wh = (const float*)d_in[2];   // [H, 4H]
    const float* b  = (const float*)d_in[3];   // [4H]
    float* out = (float*)d_out;                // [T, B, H]

    cudaFuncSetAttribute(lstm_step, cudaFuncAttributeMaxDynamicSharedMemorySize,
                         SMEM_STEP_BYTES);

    // Phase 1: precompute G = X @ Wx + b for all timesteps.
    dim3 g1(NG / 128, (TT * BSZ) / 128);       // (32, 64)
    gemm_pre<<<g1, 256>>>(x, Wx, b);

    // Phase 2: 128 sequential fused recurrent steps.
    for (int t = 0; t < TT; ++t) {
        lstm_step<<<128, STEP_THREADS, SMEM_STEP_BYTES>>>(Wh, out, t);
    }
    (void)in_sizes; (void)n_in; (void)out_size;
}